// round 14
// baseline (speedup 1.0000x reference)
#include <cuda_runtime.h>

// Shapes (fixed):
//   p1: [6,256,256] f32   bank
//   p2: [131072,256] f32  table
//   p3: [6,1] i32         row ids into p2
//   p4: [1,256] i32       gather columns
//   p5: [6,1] i32         slot (c index) per batch
//   p6: [1,256] i32       scatter columns
//   p7: [6,256,256] f32   EMA state
//   p8: [12,6,256] f32    query features
// out1: [12,6,256] f32, out2: [6,256,256] f32 (concatenated in d_out)

#define B 6
#define S 256
#define D 256
#define A 12
#define ABD (A * B * D)   // 18432

#define DT 8                      // d per block strip
#define NBLK (B * (D / DT))       // 192 blocks
#define TPB 256
#define SBS 12                    // sB row stride (floats), 16B-aligned rows
#define P8S 12                    // p8t row stride
#define REDS 97                   // red stride per c-strip (bank-spread)

// One uniform block per (b, 8-d strip). 256 threads.
//   sB[c][d] = p1 + 0.975*p7  (patched at (slot, p6[j]))
//   out1[a,b,d0+dd] = sum_c p8[a,b,c]*sB[c][dd]  via 32 c-strips of 8
//   out2[b,d0+dl,c] = sB[c][dl]
__global__ __launch_bounds__(TPB)
void fused_kernel(const float* __restrict__ p1,
                  const float* __restrict__ p2,
                  const int* __restrict__ p3,
                  const int* __restrict__ p4,
                  const int* __restrict__ p5,
                  const int* __restrict__ p6,
                  const float* __restrict__ p7,
                  const float* __restrict__ p8,
                  float* __restrict__ out1,
                  float* __restrict__ out2) {
    __shared__ __align__(16) float sB[256 * SBS];   // 12 KB add tile
    __shared__ __align__(16) float w2[31 * REDS + 96 + 1]; // p8t (3072) / red union

    const int id = blockIdx.x;
    const int b  = id / (D / DT);
    const int d0 = (id % (D / DT)) * DT;
    const int t  = threadIdx.x;

    // Patch prefetch (independent loads, overlap everything).
    const int slot = p5[b];
    const int col  = p6[t];
    const bool hit = (col >= d0) && (col < d0 + DT);
    float patch = 0.f;
    if (hit)
        patch = p2[(long long)p3[b] * D + p4[t]]
              + 0.975f * p7[(b * S + slot) * D + col];

    // Stage p8 transposed: thread t = c; 12 coalesced LDG, strided STS.
    #pragma unroll
    for (int a = 0; a < A; a++)
        w2[t * P8S + a] = p8[(a * B + b) * 256 + t];

    // Build tile: thread = (fl 0..1 [f4 over 8d], cr 0..127), 2 c-iters.
    const float* p1b = p1 + b * (S * D);
    const float* p7b = p7 + b * (S * D);
    const int fl = t & 1, cr = t >> 1;
    #pragma unroll
    for (int i = 0; i < 2; i++) {
        int c = cr + 128 * i;
        float4 v1 = ((const float4*)(p1b + c * D + d0))[fl];
        float4 v7 = ((const float4*)(p7b + c * D + d0))[fl];
        float4 val;
        val.x = fmaf(0.975f, v7.x, v1.x);
        val.y = fmaf(0.975f, v7.y, v1.y);
        val.z = fmaf(0.975f, v7.z, v1.z);
        val.w = fmaf(0.975f, v7.w, v1.w);
        *(float4*)(sB + c * SBS + fl * 4) = val;
    }
    __syncthreads();

    // Patch scattered slot-row elements.
    if (hit) sB[slot * SBS + (col - d0)] = patch;
    __syncthreads();

    // GEMM: thread = (dd 0..7, cs 0..31); c = j*32 + cs, j = 0..7.
    // 12 scalar accumulators; w from p8t as 3 float4 (dedup across dd).
    const int dd = t & 7;
    const int cs = t >> 3;
    float acc[A];
    #pragma unroll
    for (int a = 0; a < A; a++) acc[a] = 0.f;
    #pragma unroll
    for (int j = 0; j < 8; j++) {
        int c = j * 32 + cs;
        float v = sB[c * SBS + dd];
        const float* wr = w2 + c * P8S;
        float4 w0 = *(const float4*)(wr);
        float4 w1 = *(const float4*)(wr + 4);
        float4 w2v = *(const float4*)(wr + 8);
        acc[0]  = fmaf(w0.x,  v, acc[0]);
        acc[1]  = fmaf(w0.y,  v, acc[1]);
        acc[2]  = fmaf(w0.z,  v, acc[2]);
        acc[3]  = fmaf(w0.w,  v, acc[3]);
        acc[4]  = fmaf(w1.x,  v, acc[4]);
        acc[5]  = fmaf(w1.y,  v, acc[5]);
        acc[6]  = fmaf(w1.z,  v, acc[6]);
        acc[7]  = fmaf(w1.w,  v, acc[7]);
        acc[8]  = fmaf(w2v.x, v, acc[8]);
        acc[9]  = fmaf(w2v.y, v, acc[9]);
        acc[10] = fmaf(w2v.z, v, acc[10]);
        acc[11] = fmaf(w2v.w, v, acc[11]);
    }
    __syncthreads();                  // all p8t reads done

    // Strip partials into red (overlaying p8t region).
    #pragma unroll
    for (int a = 0; a < A; a++)
        w2[cs * REDS + a * 8 + dd] = acc[a];
    __syncthreads();

    // Combine 32 strips in fixed ascending order; write out1.
    if (t < A * DT) {
        float sum = 0.f;
        #pragma unroll
        for (int q = 0; q < 32; q++) sum += w2[q * REDS + t];
        int a = t >> 3, ddo = t & 7;
        out1[(a * B + b) * 256 + d0 + ddo] = sum;
    }

    // Drain out2: 2048 floats, 8 per thread, coalesced stores.
    float* out2b = out2 + b * (S * D);
    #pragma unroll
    for (int i = 0; i < 8; i++) {
        int idx = t + TPB * i;
        int dl = idx >> 8, c = idx & 255;
        out2b[(d0 + dl) * D + c] = sB[c * SBS + dl];
    }
}

extern "C" void kernel_launch(void* const* d_in, const int* in_sizes, int n_in,
                              void* d_out, int out_size) {
    const float* p1 = (const float*)d_in[0];
    const float* p2 = (const float*)d_in[1];
    const int*   p3 = (const int*)d_in[2];
    const int*   p4 = (const int*)d_in[3];
    const int*   p5 = (const int*)d_in[4];
    const int*   p6 = (const int*)d_in[5];
    const float* p7 = (const float*)d_in[6];
    const float* p8 = (const float*)d_in[7];

    float* out1 = (float*)d_out;                 // [12,6,256]
    float* out2 = out1 + ABD;                    // [6,256,256]

    fused_kernel<<<NBLK, TPB>>>(p1, p2, p3, p4, p5, p6, p7, p8, out1, out2);
}

// round 15
// speedup vs baseline: 1.0895x; 1.0895x over previous
#include <cuda_runtime.h>

// Shapes (fixed):
//   p1: [6,256,256] f32   bank
//   p2: [131072,256] f32  table
//   p3: [6,1] i32         row ids into p2
//   p4: [1,256] i32       gather columns
//   p5: [6,1] i32         slot (c index) per batch
//   p6: [1,256] i32       scatter columns
//   p7: [6,256,256] f32   EMA state
//   p8: [12,6,256] f32    query features
// out1: [12,6,256] f32, out2: [6,256,256] f32 (concatenated in d_out)

#define B 6
#define S 256
#define D 256
#define A 12
#define ABD (A * B * D)  // 18432

#define DT 16                 // d per block strip
#define NBLK (B * (D / DT))   // 96 blocks
#define TPB 512
#define STRIDE 20             // sB row stride (floats)

// One block per (b, 16-d strip). 512 threads.
//   sB[c][d] = p1 + 0.975*p7 (patched at (slot, p6[j]))
//   out2 drained EARLY (stores retire in background during GEMM)
//   out1[a,b,d0+dd] = sum_c p8[a,b,c]*sB[c][dd] (c split across 2 halves)
__global__ __launch_bounds__(TPB)
void fused_kernel(const float* __restrict__ p1,
                  const float* __restrict__ p2,
                  const int* __restrict__ p3,
                  const int* __restrict__ p4,
                  const int* __restrict__ p5,
                  const int* __restrict__ p6,
                  const float* __restrict__ p7,
                  const float* __restrict__ p8,
                  float* __restrict__ out1,
                  float* __restrict__ out2) {
    __shared__ __align__(16) float sB[256 * STRIDE];   // 20 KB add tile
    __shared__ __align__(16) float p8s[A * 256];       // 12 KB
    __shared__ float red[2 * A * DT];                  // half-sums

    const int id = blockIdx.x;
    const int b  = id / (D / DT);
    const int d0 = (id % (D / DT)) * DT;
    const int t  = threadIdx.x;

    // Patch prefetch (independent; overlaps everything below).
    const int slot = p5[b];
    bool hit = false; int col = 0; float patch = 0.f;
    if (t < 256) {
        col = p6[t];
        hit = (col >= d0) && (col < d0 + DT);
        if (hit)
            patch = p2[(long long)p3[b] * D + p4[t]]
                  + 0.975f * p7[(b * S + slot) * D + col];
    }

    // Stage p8: 12*256 floats, 6 per thread, coalesced.
    #pragma unroll
    for (int i = 0; i < 6; i++) {
        int idx = t + TPB * i;
        p8s[idx] = p8[((idx >> 8) * B + b) * 256 + (idx & 255)];
    }

    // Build tile: thread = (f4 lane fl 0..3, c-row cr 0..127), 2 c-iters.
    const float* p1b = p1 + b * (S * D);
    const float* p7b = p7 + b * (S * D);
    const int fl = t & 3, cr = t >> 2;
    #pragma unroll
    for (int i = 0; i < 2; i++) {
        int c = cr + 128 * i;
        float4 v1 = ((const float4*)(p1b + c * D + d0))[fl];
        float4 v7 = ((const float4*)(p7b + c * D + d0))[fl];
        float4 val;
        val.x = fmaf(0.975f, v7.x, v1.x);
        val.y = fmaf(0.975f, v7.y, v1.y);
        val.z = fmaf(0.975f, v7.z, v1.z);
        val.w = fmaf(0.975f, v7.w, v1.w);
        *(float4*)(sB + c * STRIDE + fl * 4) = val;
    }
    __syncthreads();

    // Patch scattered slot-row elements.
    if (hit) sB[slot * STRIDE + (col - d0)] = patch;
    __syncthreads();

    // EARLY drain of out2: stores issue now, retire during the GEMM below.
    float* out2b = out2 + b * (S * D);
    #pragma unroll
    for (int i = 0; i < 8; i++) {
        int idx = t + TPB * i;            // 4096 floats = 16 rows x 256
        int dl = idx >> 8, c = idx & 255;
        out2b[(d0 + dl) * D + c] = sB[c * STRIDE + dl];
    }

    // GEMM: t<384. dd = t&15, g = t>>4 (0..23), a = g%12, h = g/12.
    if (t < 2 * A * DT) {
        const int dd = t & 15;
        const int g  = t >> 4;
        const int a  = g % A;
        const int h  = g / A;
        const float* pr = p8s + a * 256 + h * 128;
        const float* sc = sB + h * 128 * STRIDE + dd;
        float a0 = 0.f, a1 = 0.f, a2 = 0.f, a3 = 0.f;
        #pragma unroll 8
        for (int c = 0; c < 128; c += 4) {
            float4 w = *(const float4*)(pr + c);
            a0 = fmaf(w.x, sc[(c + 0) * STRIDE], a0);
            a1 = fmaf(w.y, sc[(c + 1) * STRIDE], a1);
            a2 = fmaf(w.z, sc[(c + 2) * STRIDE], a2);
            a3 = fmaf(w.w, sc[(c + 3) * STRIDE], a3);
        }
        red[h * (A * DT) + a * DT + dd] = (a0 + a1) + (a2 + a3);
    }
    __syncthreads();

    // Combine halves (fixed order) and write out1.
    if (t < A * DT) {
        float sum = red[t] + red[A * DT + t];
        int a = t >> 4, dd = t & 15;
        out1[(a * B + b) * 256 + d0 + dd] = sum;
    }
}

extern "C" void kernel_launch(void* const* d_in, const int* in_sizes, int n_in,
                              void* d_out, int out_size) {
    const float* p1 = (const float*)d_in[0];
    const float* p2 = (const float*)d_in[1];
    const int*   p3 = (const int*)d_in[2];
    const int*   p4 = (const int*)d_in[3];
    const int*   p5 = (const int*)d_in[4];
    const int*   p6 = (const int*)d_in[5];
    const float* p7 = (const float*)d_in[6];
    const float* p8 = (const float*)d_in[7];

    float* out1 = (float*)d_out;                 // [12,6,256]
    float* out2 = out1 + ABD;                    // [6,256,256]

    fused_kernel<<<NBLK, TPB>>>(p1, p2, p3, p4, p5, p6, p7, p8, out1, out2);
}